// round 9
// baseline (speedup 1.0000x reference)
#include <cuda_runtime.h>

// Problem constants (fixed by the reference):
//   N=100000 nodes, E=1600000 edges, IN=128, HID=64, OUT=8, B=16384
// NOTE: reference uses jnp.int64 but JAX x64 is disabled -> edge_index/idx are int32.
#define N_MAX 100000
#define E_MAX 1600000

// ---------------- scratch (device globals; no allocation allowed) ----------
__device__ __align__(256) int   g_deg[N_MAX];
__device__ __align__(256) int   g_rowstart[N_MAX + 1];
__device__ __align__(256) int   g_cursor[N_MAX];
__device__ __align__(256) int   g_srclist[E_MAX];
__device__ __align__(256) int   g_blocksums[512];
__device__ __align__(256) float g_y[(size_t)N_MAX * 128];  // [N][0:64)=x@W1_l, [64:128)=x@W1_r
__device__ __align__(256) float g_h[(size_t)N_MAX * 64];   // layer-1 activations
__device__ __align__(256) float g_z[(size_t)N_MAX * 8];    // h @ W2_l

// ---------------- stream/event for forked capture (created pre-main) --------
static cudaStream_t g_s2 = 0;
static cudaEvent_t  g_ev_fork = 0, g_ev_join = 0;
namespace {
struct StreamInit {
    StreamInit() {
        cudaStreamCreateWithFlags(&g_s2, cudaStreamNonBlocking);
        cudaEventCreateWithFlags(&g_ev_fork, cudaEventDisableTiming);
        cudaEventCreateWithFlags(&g_ev_join, cudaEventDisableTiming);
    }
};
static StreamInit g_stream_init;
}

// ---------------- CSR build --------------------------------------------------
__global__ void hist_kernel(const int* __restrict__ dst, int e) {
    int i = blockIdx.x * blockDim.x + threadIdx.x;
    if (i < e) atomicAdd(&g_deg[dst[i]], 1);
}

// per-block exclusive scan over 256 elements
__global__ void __launch_bounds__(256) scan_block_kernel(int n) {
    __shared__ int s[256];
    int i = blockIdx.x * 256 + threadIdx.x;
    int v = (i < n) ? g_deg[i] : 0;
    s[threadIdx.x] = v;
    __syncthreads();
#pragma unroll
    for (int off = 1; off < 256; off <<= 1) {
        int t = 0;
        if ((int)threadIdx.x >= off) t = s[threadIdx.x - off];
        __syncthreads();
        if ((int)threadIdx.x >= off) s[threadIdx.x] += t;
        __syncthreads();
    }
    if (i < n) g_rowstart[i] = s[threadIdx.x] - v;  // exclusive within block
    if (threadIdx.x == 255) g_blocksums[blockIdx.x] = s[255];
}

// single-block exclusive scan over up to 512 block sums
__global__ void __launch_bounds__(512) scan_sums_kernel(int nb) {
    __shared__ int s[512];
    int v = ((int)threadIdx.x < nb) ? g_blocksums[threadIdx.x] : 0;
    s[threadIdx.x] = v;
    __syncthreads();
#pragma unroll
    for (int off = 1; off < 512; off <<= 1) {
        int t = 0;
        if ((int)threadIdx.x >= off) t = s[threadIdx.x - off];
        __syncthreads();
        if ((int)threadIdx.x >= off) s[threadIdx.x] += t;
        __syncthreads();
    }
    if ((int)threadIdx.x < nb) g_blocksums[threadIdx.x] = s[threadIdx.x] - v;  // exclusive
}

__global__ void __launch_bounds__(256) add_offsets_kernel(int n, int e) {
    int i = blockIdx.x * 256 + threadIdx.x;
    if (i < n) {
        int r = g_rowstart[i] + g_blocksums[blockIdx.x];
        g_rowstart[i] = r;
        g_cursor[i]   = r;
    }
    if (blockIdx.x == 0 && threadIdx.x == 0) g_rowstart[n] = e;
}

__global__ void scatter_kernel(const int* __restrict__ src,
                               const int* __restrict__ dst, int e) {
    int i = blockIdx.x * blockDim.x + threadIdx.x;
    if (i < e) {
        int d = dst[i];
        int p = atomicAdd(&g_cursor[d], 1);
        g_srclist[p] = src[i];
    }
}

// ---------------- GEMM1: y = x @ [W1_l | W1_r]  (N x 128 @ 128 x 128) -------
// Tile: BM=128, BN=128, BK=16; 256 threads, 8x8 register tile.
// Double-buffered smem (one __syncthreads per k-block).
__global__ void __launch_bounds__(256) gemm1_kernel(const float* __restrict__ x,
                                                    const float* __restrict__ Wl,
                                                    const float* __restrict__ Wr,
                                                    int n) {
    __shared__ __align__(16) float xs[2][16][132];  // k-major, padded
    __shared__ __align__(16) float ws[2][16][128];
    int tid = threadIdx.x;
    int row0 = blockIdx.x * 128;
    int tx = tid & 15;  // cols [tx*8, tx*8+8)
    int ty = tid >> 4;  // rows [ty*8, ty*8+8)

    int xr0 = tid >> 2;  // 0..63
    int xc4 = tid & 3;   // float4 slot within 16-wide k slab
    int wk0 = tid >> 5;  // 0..7
    int wc4 = tid & 31;  // 0..31 (c4<16 -> Wl, else Wr)

    int gr0 = row0 + xr0;
    int gr1 = gr0 + 64;

    float acc[8][8];
#pragma unroll
    for (int r = 0; r < 8; r++)
#pragma unroll
        for (int c = 0; c < 8; c++) acc[r][c] = 0.0f;

    float4 xv0, xv1, wv0, wv1;
    // prologue: load kb=0 into regs, store to buf 0
    {
        xv0 = make_float4(0.f, 0.f, 0.f, 0.f);
        xv1 = xv0;
        if (gr0 < n) xv0 = *(const float4*)(x + (size_t)gr0 * 128 + xc4 * 4);
        if (gr1 < n) xv1 = *(const float4*)(x + (size_t)gr1 * 128 + xc4 * 4);
        if (wc4 < 16) {
            wv0 = *(const float4*)(Wl + wk0 * 64 + wc4 * 4);
            wv1 = *(const float4*)(Wl + (wk0 + 8) * 64 + wc4 * 4);
        } else {
            wv0 = *(const float4*)(Wr + wk0 * 64 + (wc4 - 16) * 4);
            wv1 = *(const float4*)(Wr + (wk0 + 8) * 64 + (wc4 - 16) * 4);
        }
        xs[0][xc4 * 4 + 0][xr0] = xv0.x; xs[0][xc4 * 4 + 1][xr0] = xv0.y;
        xs[0][xc4 * 4 + 2][xr0] = xv0.z; xs[0][xc4 * 4 + 3][xr0] = xv0.w;
        xs[0][xc4 * 4 + 0][xr0 + 64] = xv1.x; xs[0][xc4 * 4 + 1][xr0 + 64] = xv1.y;
        xs[0][xc4 * 4 + 2][xr0 + 64] = xv1.z; xs[0][xc4 * 4 + 3][xr0 + 64] = xv1.w;
        *(float4*)&ws[0][wk0][wc4 * 4] = wv0;
        *(float4*)&ws[0][wk0 + 8][wc4 * 4] = wv1;
    }
    __syncthreads();

#pragma unroll
    for (int i = 0; i < 8; i++) {
        int cur = i & 1;
        if (i < 7) {
            int kb = (i + 1) * 16;
            xv0 = make_float4(0.f, 0.f, 0.f, 0.f);
            xv1 = xv0;
            if (gr0 < n) xv0 = *(const float4*)(x + (size_t)gr0 * 128 + kb + xc4 * 4);
            if (gr1 < n) xv1 = *(const float4*)(x + (size_t)gr1 * 128 + kb + xc4 * 4);
            if (wc4 < 16) {
                wv0 = *(const float4*)(Wl + (kb + wk0) * 64 + wc4 * 4);
                wv1 = *(const float4*)(Wl + (kb + wk0 + 8) * 64 + wc4 * 4);
            } else {
                wv0 = *(const float4*)(Wr + (kb + wk0) * 64 + (wc4 - 16) * 4);
                wv1 = *(const float4*)(Wr + (kb + wk0 + 8) * 64 + (wc4 - 16) * 4);
            }
        }
#pragma unroll
        for (int k = 0; k < 16; k++) {
            float4 a0 = *(float4*)&xs[cur][k][ty * 8];
            float4 a1 = *(float4*)&xs[cur][k][ty * 8 + 4];
            float4 b0 = *(float4*)&ws[cur][k][tx * 8];
            float4 b1 = *(float4*)&ws[cur][k][tx * 8 + 4];
            float av[8] = {a0.x, a0.y, a0.z, a0.w, a1.x, a1.y, a1.z, a1.w};
            float bv[8] = {b0.x, b0.y, b0.z, b0.w, b1.x, b1.y, b1.z, b1.w};
#pragma unroll
            for (int r = 0; r < 8; r++)
#pragma unroll
                for (int c = 0; c < 8; c++) acc[r][c] += av[r] * bv[c];
        }
        if (i < 7) {
            int nxt = cur ^ 1;
            xs[nxt][xc4 * 4 + 0][xr0] = xv0.x; xs[nxt][xc4 * 4 + 1][xr0] = xv0.y;
            xs[nxt][xc4 * 4 + 2][xr0] = xv0.z; xs[nxt][xc4 * 4 + 3][xr0] = xv0.w;
            xs[nxt][xc4 * 4 + 0][xr0 + 64] = xv1.x; xs[nxt][xc4 * 4 + 1][xr0 + 64] = xv1.y;
            xs[nxt][xc4 * 4 + 2][xr0 + 64] = xv1.z; xs[nxt][xc4 * 4 + 3][xr0 + 64] = xv1.w;
            *(float4*)&ws[nxt][wk0][wc4 * 4] = wv0;
            *(float4*)&ws[nxt][wk0 + 8][wc4 * 4] = wv1;
        }
        __syncthreads();
    }

#pragma unroll
    for (int r = 0; r < 8; r++) {
        int gr = row0 + ty * 8 + r;
        if (gr < n) {
            *(float4*)(g_y + (size_t)gr * 128 + tx * 8) =
                make_float4(acc[r][0], acc[r][1], acc[r][2], acc[r][3]);
            *(float4*)(g_y + (size_t)gr * 128 + tx * 8 + 4) =
                make_float4(acc[r][4], acc[r][5], acc[r][6], acc[r][7]);
        }
    }
}

// ---------------- layer 1 combine + z -----------------------------------
// h = dropout(relu(agg/deg + y_r + b1)); z = h @ W2_l (warp butterfly reduce).
// 32 threads per node (float2 per thread), 8 nodes per 256-thread block.
__global__ void __launch_bounds__(256) layer1_kernel(const float* __restrict__ b1,
                                                     const float* __restrict__ mask,
                                                     const float* __restrict__ W2l,
                                                     int n) {
    __shared__ __align__(16) float w2[512];
    __shared__ float b1s[64];
    for (int i = threadIdx.x; i < 512; i += 256) w2[i] = W2l[i];
    if (threadIdx.x < 64) b1s[threadIdx.x] = b1[threadIdx.x];
    __syncthreads();

    int node = blockIdx.x * 8 + (threadIdx.x >> 5);
    int lane = threadIdx.x & 31;
    int d = lane * 2;
    if (node >= n) return;
    int s = g_rowstart[node];
    int epos = g_rowstart[node + 1];
    float2 a0 = make_float2(0.f, 0.f), a1 = make_float2(0.f, 0.f);
    float2 a2 = make_float2(0.f, 0.f), a3 = make_float2(0.f, 0.f);
    int e = s;
    for (; e + 4 <= epos; e += 4) {
        int s0 = g_srclist[e], s1 = g_srclist[e + 1];
        int s2 = g_srclist[e + 2], s3 = g_srclist[e + 3];
        float2 v0 = *(const float2*)(g_y + (size_t)s0 * 128 + d);
        float2 v1 = *(const float2*)(g_y + (size_t)s1 * 128 + d);
        float2 v2 = *(const float2*)(g_y + (size_t)s2 * 128 + d);
        float2 v3 = *(const float2*)(g_y + (size_t)s3 * 128 + d);
        a0.x += v0.x; a0.y += v0.y;
        a1.x += v1.x; a1.y += v1.y;
        a2.x += v2.x; a2.y += v2.y;
        a3.x += v3.x; a3.y += v3.y;
    }
    for (; e < epos; e++) {
        float2 v = *(const float2*)(g_y + (size_t)g_srclist[e] * 128 + d);
        a0.x += v.x; a0.y += v.y;
    }
    float sx = (a0.x + a1.x) + (a2.x + a3.x);
    float sy = (a0.y + a1.y) + (a2.y + a3.y);
    float inv = 1.0f / fmaxf((float)(epos - s), 1.0f);
    float2 yr = *(const float2*)(g_y + (size_t)node * 128 + 64 + d);
    float hx = sx * inv + yr.x + b1s[d];
    float hy = sy * inv + yr.y + b1s[d + 1];
    hx = fmaxf(hx, 0.0f);
    hy = fmaxf(hy, 0.0f);
    float2 mk = *(const float2*)(mask + (size_t)node * 64 + d);
    hx = (mk.x > 0.5f) ? hx * 2.0f : 0.0f;
    hy = (mk.y > 0.5f) ? hy * 2.0f : 0.0f;
    *(float2*)(g_h + (size_t)node * 64 + d) = make_float2(hx, hy);

    // z = h @ W2_l : per-lane partials over its 2 dims, butterfly across warp
    float zacc[8];
#pragma unroll
    for (int j = 0; j < 8; j++)
        zacc[j] = hx * w2[d * 8 + j] + hy * w2[(d + 1) * 8 + j];
#pragma unroll
    for (int off = 16; off > 0; off >>= 1)
#pragma unroll
        for (int j = 0; j < 8; j++)
            zacc[j] += __shfl_xor_sync(0xffffffffu, zacc[j], off);
    if (lane == 0) {
        float4* zp = (float4*)(g_z + (size_t)node * 8);
        zp[0] = make_float4(zacc[0], zacc[1], zacc[2], zacc[3]);
        zp[1] = make_float4(zacc[4], zacc[5], zacc[6], zacc[7]);
    }
}

// ---------------- output: out[b] = agg2(idx[b])/deg + h[idx[b]]@W2_r + b2 ---
__global__ void __launch_bounds__(256) out_kernel(const int* __restrict__ idx,
                                                  const float* __restrict__ W2r,
                                                  const float* __restrict__ b2,
                                                  float* __restrict__ out,
                                                  int bcnt) {
    __shared__ __align__(16) float w[512];
    __shared__ float bb[8];
    for (int i = threadIdx.x; i < 512; i += 256) w[i] = W2r[i];
    if (threadIdx.x < 8) bb[threadIdx.x] = b2[threadIdx.x];
    __syncthreads();
    int b = blockIdx.x * 32 + (threadIdx.x >> 3);
    int j = threadIdx.x & 7;
    if (b >= bcnt) return;
    int node = idx[b];
    int s = g_rowstart[node];
    int epos = g_rowstart[node + 1];
    float a0 = 0.f, a1 = 0.f, a2 = 0.f, a3 = 0.f;
    int e = s;
    for (; e + 4 <= epos; e += 4) {
        int s0 = g_srclist[e], s1 = g_srclist[e + 1];
        int s2 = g_srclist[e + 2], s3 = g_srclist[e + 3];
        a0 += g_z[(size_t)s0 * 8 + j];
        a1 += g_z[(size_t)s1 * 8 + j];
        a2 += g_z[(size_t)s2 * 8 + j];
        a3 += g_z[(size_t)s3 * 8 + j];
    }
    for (; e < epos; e++) a0 += g_z[(size_t)g_srclist[e] * 8 + j];
    float acc = ((a0 + a1) + (a2 + a3)) / fmaxf((float)(epos - s), 1.0f);
    const float* hr = g_h + (size_t)node * 64;
    float dot = 0.f;
#pragma unroll
    for (int k = 0; k < 64; k++) dot += hr[k] * w[k * 8 + j];
    out[(size_t)b * 8 + j] = acc + dot + bb[j];
}

// ---------------- launch -----------------------------------------------------
extern "C" void kernel_launch(void* const* d_in, const int* in_sizes, int n_in,
                              void* d_out, int out_size) {
    const float* x    = (const float*)d_in[0];
    const int*   edge = (const int*)d_in[1];   // int32 (JAX x64 disabled)
    const int*   idx  = (const int*)d_in[2];   // int32
    const float* mask = (const float*)d_in[3];
    const float* W1l  = (const float*)d_in[4];
    const float* W1r  = (const float*)d_in[5];
    const float* b1   = (const float*)d_in[6];
    const float* W2l  = (const float*)d_in[7];
    const float* W2r  = (const float*)d_in[8];
    const float* b2   = (const float*)d_in[9];
    float* out = (float*)d_out;

    int n = in_sizes[0] / 128;
    int e = in_sizes[1] / 2;
    int bcnt = in_sizes[2];
    const int* src = edge;
    const int* dst = edge + e;

    int nb = (n + 255) / 256;  // 391 blocks for N=100000 (fits 512-wide sums scan)

    void* deg_ptr = 0;
    cudaGetSymbolAddress(&deg_ptr, g_deg);

    // fork: CSR chain on side stream, concurrent with gemm1 on main stream
    cudaEventRecord(g_ev_fork, 0);
    cudaStreamWaitEvent(g_s2, g_ev_fork, 0);

    cudaMemsetAsync(deg_ptr, 0, n * sizeof(int), g_s2);
    hist_kernel<<<(e + 255) / 256, 256, 0, g_s2>>>(dst, e);
    scan_block_kernel<<<nb, 256, 0, g_s2>>>(n);
    scan_sums_kernel<<<1, 512, 0, g_s2>>>(nb);
    add_offsets_kernel<<<nb, 256, 0, g_s2>>>(n, e);
    scatter_kernel<<<(e + 255) / 256, 256, 0, g_s2>>>(src, dst, e);
    cudaEventRecord(g_ev_join, g_s2);

    gemm1_kernel<<<(n + 127) / 128, 256>>>(x, W1l, W1r, n);

    // join: layer1 needs both CSR and gemm1
    cudaStreamWaitEvent(0, g_ev_join, 0);
    layer1_kernel<<<(n + 7) / 8, 256>>>(b1, mask, W2l, n);
    out_kernel<<<(bcnt + 31) / 32, 256>>>(idx, W2r, b2, out, bcnt);
}

// round 10
// speedup vs baseline: 1.1276x; 1.1276x over previous
#include <cuda_runtime.h>

// Problem constants (fixed by the reference):
//   N=100000 nodes, E=1600000 edges, IN=128, HID=64, OUT=8, B=16384
// NOTE: reference uses jnp.int64 but JAX x64 is disabled -> edge_index/idx are int32.
#define N_MAX 100000
#define E_MAX 1600000

// ---------------- scratch (device globals; no allocation allowed) ----------
__device__ __align__(256) int   g_deg[N_MAX];
__device__ __align__(256) int   g_rowstart[N_MAX + 1];
__device__ __align__(256) int   g_cursor[N_MAX];
__device__ __align__(256) int   g_srclist[E_MAX];
__device__ __align__(256) int   g_blocksums[512];
__device__ __align__(256) float g_y[(size_t)N_MAX * 128];  // [N][0:64)=x@W1_l, [64:128)=x@W1_r
__device__ __align__(256) float g_h[(size_t)N_MAX * 64];   // layer-1 activations
__device__ __align__(256) float g_z[(size_t)N_MAX * 8];    // h @ W2_l

// ---------------- stream/event for forked capture (created pre-main) --------
static cudaStream_t g_s2 = 0;
static cudaEvent_t  g_ev_fork = 0, g_ev_join = 0;
namespace {
struct StreamInit {
    StreamInit() {
        cudaStreamCreateWithFlags(&g_s2, cudaStreamNonBlocking);
        cudaEventCreateWithFlags(&g_ev_fork, cudaEventDisableTiming);
        cudaEventCreateWithFlags(&g_ev_join, cudaEventDisableTiming);
    }
};
static StreamInit g_stream_init;
}

// ---------------- CSR build --------------------------------------------------
__global__ void hist_kernel(const int* __restrict__ dst, int e) {
    int i = blockIdx.x * blockDim.x + threadIdx.x;
    if (i < e) atomicAdd(&g_deg[dst[i]], 1);
}

// per-block exclusive scan over 256 elements
__global__ void __launch_bounds__(256) scan_block_kernel(int n) {
    __shared__ int s[256];
    int i = blockIdx.x * 256 + threadIdx.x;
    int v = (i < n) ? g_deg[i] : 0;
    s[threadIdx.x] = v;
    __syncthreads();
#pragma unroll
    for (int off = 1; off < 256; off <<= 1) {
        int t = 0;
        if ((int)threadIdx.x >= off) t = s[threadIdx.x - off];
        __syncthreads();
        if ((int)threadIdx.x >= off) s[threadIdx.x] += t;
        __syncthreads();
    }
    if (i < n) g_rowstart[i] = s[threadIdx.x] - v;  // exclusive within block
    if (threadIdx.x == 255) g_blocksums[blockIdx.x] = s[255];
}

// single-block exclusive scan over up to 512 block sums
__global__ void __launch_bounds__(512) scan_sums_kernel(int nb) {
    __shared__ int s[512];
    int v = ((int)threadIdx.x < nb) ? g_blocksums[threadIdx.x] : 0;
    s[threadIdx.x] = v;
    __syncthreads();
#pragma unroll
    for (int off = 1; off < 512; off <<= 1) {
        int t = 0;
        if ((int)threadIdx.x >= off) t = s[threadIdx.x - off];
        __syncthreads();
        if ((int)threadIdx.x >= off) s[threadIdx.x] += t;
        __syncthreads();
    }
    if ((int)threadIdx.x < nb) g_blocksums[threadIdx.x] = s[threadIdx.x] - v;  // exclusive
}

__global__ void __launch_bounds__(256) add_offsets_kernel(int n, int e) {
    int i = blockIdx.x * 256 + threadIdx.x;
    if (i < n) {
        int r = g_rowstart[i] + g_blocksums[blockIdx.x];
        g_rowstart[i] = r;
        g_cursor[i]   = r;
    }
    if (blockIdx.x == 0 && threadIdx.x == 0) g_rowstart[n] = e;
}

__global__ void scatter_kernel(const int* __restrict__ src,
                               const int* __restrict__ dst, int e) {
    int i = blockIdx.x * blockDim.x + threadIdx.x;
    if (i < e) {
        int d = dst[i];
        int p = atomicAdd(&g_cursor[d], 1);
        g_srclist[p] = src[i];
    }
}

// ---------------- GEMM1: y = x @ [W1_l | W1_r]  (N x 128 @ 128 x 128) -------
// Tile: BM=128 rows, BN=128 cols, BK=16. 256 threads; each thread: 8x8 outputs.
// Single-buffered smem (R7 version: proven fastest so far).
__global__ void __launch_bounds__(256) gemm1_kernel(const float* __restrict__ x,
                                                    const float* __restrict__ Wl,
                                                    const float* __restrict__ Wr,
                                                    int n) {
    __shared__ __align__(16) float xs[16][132];  // k-major, padded: 8448 B
    __shared__ __align__(16) float ws[16][128];  // 8192 B
    int tid = threadIdx.x;
    int row0 = blockIdx.x * 128;
    int tx = tid & 15;  // cols [tx*8, tx*8+8)
    int ty = tid >> 4;  // rows [ty*8, ty*8+8)

    float acc[8][8];
#pragma unroll
    for (int r = 0; r < 8; r++)
#pragma unroll
        for (int c = 0; c < 8; c++) acc[r][c] = 0.0f;

    int xr0 = tid >> 2;  // 0..63
    int xc4 = tid & 3;   // float4 slot within 16-wide k slab
    int wk0 = tid >> 5;  // 0..7
    int wc4 = tid & 31;  // 0..31 (c4<16 -> Wl, else Wr)

    for (int kb = 0; kb < 128; kb += 16) {
        // load x tile 128x16 -> xs[k][row] (transposed store)
#pragma unroll
        for (int it = 0; it < 2; it++) {
            int row = xr0 + it * 64;
            int gr = row0 + row;
            float4 v = make_float4(0.f, 0.f, 0.f, 0.f);
            if (gr < n) v = *(const float4*)(x + (size_t)gr * 128 + kb + xc4 * 4);
            xs[xc4 * 4 + 0][row] = v.x;
            xs[xc4 * 4 + 1][row] = v.y;
            xs[xc4 * 4 + 2][row] = v.z;
            xs[xc4 * 4 + 3][row] = v.w;
        }
        // load W tile 16x128 (cols 0:64 = Wl, 64:128 = Wr)
#pragma unroll
        for (int it = 0; it < 2; it++) {
            int k = wk0 + it * 8;
            float4 v;
            if (wc4 < 16) v = *(const float4*)(Wl + (kb + k) * 64 + wc4 * 4);
            else          v = *(const float4*)(Wr + (kb + k) * 64 + (wc4 - 16) * 4);
            *(float4*)&ws[k][wc4 * 4] = v;
        }
        __syncthreads();
#pragma unroll
        for (int k = 0; k < 16; k++) {
            float4 a0 = *(float4*)&xs[k][ty * 8];
            float4 a1 = *(float4*)&xs[k][ty * 8 + 4];
            float4 b0 = *(float4*)&ws[k][tx * 8];
            float4 b1 = *(float4*)&ws[k][tx * 8 + 4];
            float av[8] = {a0.x, a0.y, a0.z, a0.w, a1.x, a1.y, a1.z, a1.w};
            float bv[8] = {b0.x, b0.y, b0.z, b0.w, b1.x, b1.y, b1.z, b1.w};
#pragma unroll
            for (int r = 0; r < 8; r++)
#pragma unroll
                for (int c = 0; c < 8; c++) acc[r][c] += av[r] * bv[c];
        }
        __syncthreads();
    }
#pragma unroll
    for (int r = 0; r < 8; r++) {
        int gr = row0 + ty * 8 + r;
        if (gr < n) {
            *(float4*)(g_y + (size_t)gr * 128 + tx * 8) =
                make_float4(acc[r][0], acc[r][1], acc[r][2], acc[r][3]);
            *(float4*)(g_y + (size_t)gr * 128 + tx * 8 + 4) =
                make_float4(acc[r][4], acc[r][5], acc[r][6], acc[r][7]);
        }
    }
}

// ---------------- layer 1 combine + z -----------------------------------
// h = dropout(relu(agg/deg + y_r + b1)); z = h @ W2_l (warp butterfly reduce).
// 32 threads per node (float2 per thread), 8 nodes per 256-thread block.
__global__ void __launch_bounds__(256) layer1_kernel(const float* __restrict__ b1,
                                                     const float* __restrict__ mask,
                                                     const float* __restrict__ W2l,
                                                     int n) {
    __shared__ __align__(16) float w2[512];
    __shared__ float b1s[64];
    for (int i = threadIdx.x; i < 512; i += 256) w2[i] = W2l[i];
    if (threadIdx.x < 64) b1s[threadIdx.x] = b1[threadIdx.x];
    __syncthreads();

    int node = blockIdx.x * 8 + (threadIdx.x >> 5);
    int lane = threadIdx.x & 31;
    int d = lane * 2;
    if (node >= n) return;
    int s = g_rowstart[node];
    int epos = g_rowstart[node + 1];
    float2 a0 = make_float2(0.f, 0.f), a1 = make_float2(0.f, 0.f);
    float2 a2 = make_float2(0.f, 0.f), a3 = make_float2(0.f, 0.f);
    int e = s;
    for (; e + 4 <= epos; e += 4) {
        int s0 = g_srclist[e], s1 = g_srclist[e + 1];
        int s2 = g_srclist[e + 2], s3 = g_srclist[e + 3];
        float2 v0 = *(const float2*)(g_y + (size_t)s0 * 128 + d);
        float2 v1 = *(const float2*)(g_y + (size_t)s1 * 128 + d);
        float2 v2 = *(const float2*)(g_y + (size_t)s2 * 128 + d);
        float2 v3 = *(const float2*)(g_y + (size_t)s3 * 128 + d);
        a0.x += v0.x; a0.y += v0.y;
        a1.x += v1.x; a1.y += v1.y;
        a2.x += v2.x; a2.y += v2.y;
        a3.x += v3.x; a3.y += v3.y;
    }
    for (; e < epos; e++) {
        float2 v = *(const float2*)(g_y + (size_t)g_srclist[e] * 128 + d);
        a0.x += v.x; a0.y += v.y;
    }
    float sx = (a0.x + a1.x) + (a2.x + a3.x);
    float sy = (a0.y + a1.y) + (a2.y + a3.y);
    float inv = 1.0f / fmaxf((float)(epos - s), 1.0f);
    float2 yr = *(const float2*)(g_y + (size_t)node * 128 + 64 + d);
    float hx = sx * inv + yr.x + b1s[d];
    float hy = sy * inv + yr.y + b1s[d + 1];
    hx = fmaxf(hx, 0.0f);
    hy = fmaxf(hy, 0.0f);
    float2 mk = *(const float2*)(mask + (size_t)node * 64 + d);
    hx = (mk.x > 0.5f) ? hx * 2.0f : 0.0f;
    hy = (mk.y > 0.5f) ? hy * 2.0f : 0.0f;
    *(float2*)(g_h + (size_t)node * 64 + d) = make_float2(hx, hy);

    // z = h @ W2_l : per-lane partials over its 2 dims, butterfly across warp
    float zacc[8];
#pragma unroll
    for (int j = 0; j < 8; j++)
        zacc[j] = hx * w2[d * 8 + j] + hy * w2[(d + 1) * 8 + j];
#pragma unroll
    for (int off = 16; off > 0; off >>= 1)
#pragma unroll
        for (int j = 0; j < 8; j++)
            zacc[j] += __shfl_xor_sync(0xffffffffu, zacc[j], off);
    if (lane == 0) {
        float4* zp = (float4*)(g_z + (size_t)node * 8);
        zp[0] = make_float4(zacc[0], zacc[1], zacc[2], zacc[3]);
        zp[1] = make_float4(zacc[4], zacc[5], zacc[6], zacc[7]);
    }
}

// ---------------- output: out[b] = agg2(idx[b])/deg + h[idx[b]]@W2_r + b2 ---
__global__ void __launch_bounds__(256) out_kernel(const int* __restrict__ idx,
                                                  const float* __restrict__ W2r,
                                                  const float* __restrict__ b2,
                                                  float* __restrict__ out,
                                                  int bcnt) {
    __shared__ __align__(16) float w[512];
    __shared__ float bb[8];
    for (int i = threadIdx.x; i < 512; i += 256) w[i] = W2r[i];
    if (threadIdx.x < 8) bb[threadIdx.x] = b2[threadIdx.x];
    __syncthreads();
    int b = blockIdx.x * 32 + (threadIdx.x >> 3);
    int j = threadIdx.x & 7;
    if (b >= bcnt) return;
    int node = idx[b];
    int s = g_rowstart[node];
    int epos = g_rowstart[node + 1];
    float a0 = 0.f, a1 = 0.f, a2 = 0.f, a3 = 0.f;
    int e = s;
    for (; e + 4 <= epos; e += 4) {
        int s0 = g_srclist[e], s1 = g_srclist[e + 1];
        int s2 = g_srclist[e + 2], s3 = g_srclist[e + 3];
        a0 += g_z[(size_t)s0 * 8 + j];
        a1 += g_z[(size_t)s1 * 8 + j];
        a2 += g_z[(size_t)s2 * 8 + j];
        a3 += g_z[(size_t)s3 * 8 + j];
    }
    for (; e < epos; e++) a0 += g_z[(size_t)g_srclist[e] * 8 + j];
    float acc = ((a0 + a1) + (a2 + a3)) / fmaxf((float)(epos - s), 1.0f);
    const float* hr = g_h + (size_t)node * 64;
    float dot = 0.f;
#pragma unroll
    for (int k = 0; k < 64; k++) dot += hr[k] * w[k * 8 + j];
    out[(size_t)b * 8 + j] = acc + dot + bb[j];
}

// ---------------- launch -----------------------------------------------------
extern "C" void kernel_launch(void* const* d_in, const int* in_sizes, int n_in,
                              void* d_out, int out_size) {
    const float* x    = (const float*)d_in[0];
    const int*   edge = (const int*)d_in[1];   // int32 (JAX x64 disabled)
    const int*   idx  = (const int*)d_in[2];   // int32
    const float* mask = (const float*)d_in[3];
    const float* W1l  = (const float*)d_in[4];
    const float* W1r  = (const float*)d_in[5];
    const float* b1   = (const float*)d_in[6];
    const float* W2l  = (const float*)d_in[7];
    const float* W2r  = (const float*)d_in[8];
    const float* b2   = (const float*)d_in[9];
    float* out = (float*)d_out;

    int n = in_sizes[0] / 128;
    int e = in_sizes[1] / 2;
    int bcnt = in_sizes[2];
    const int* src = edge;
    const int* dst = edge + e;

    int nb = (n + 255) / 256;  // 391 blocks for N=100000 (fits 512-wide sums scan)

    void* deg_ptr = 0;
    cudaGetSymbolAddress(&deg_ptr, g_deg);

    // fork: CSR chain on side stream, concurrent with gemm1 on main stream
    cudaEventRecord(g_ev_fork, 0);
    cudaStreamWaitEvent(g_s2, g_ev_fork, 0);

    cudaMemsetAsync(deg_ptr, 0, n * sizeof(int), g_s2);
    hist_kernel<<<(e + 255) / 256, 256, 0, g_s2>>>(dst, e);
    scan_block_kernel<<<nb, 256, 0, g_s2>>>(n);
    scan_sums_kernel<<<1, 512, 0, g_s2>>>(nb);
    add_offsets_kernel<<<nb, 256, 0, g_s2>>>(n, e);
    scatter_kernel<<<(e + 255) / 256, 256, 0, g_s2>>>(src, dst, e);
    cudaEventRecord(g_ev_join, g_s2);

    gemm1_kernel<<<(n + 127) / 128, 256>>>(x, W1l, W1r, n);

    // join: layer1 needs both CSR and gemm1
    cudaStreamWaitEvent(0, g_ev_join, 0);
    layer1_kernel<<<(n + 7) / 8, 256>>>(b1, mask, W2l, n);
    out_kernel<<<(bcnt + 31) / 32, 256>>>(idx, W2r, b2, out, bcnt);
}